// round 1
// baseline (speedup 1.0000x reference)
#include <cuda_runtime.h>

#define NB 16
#define NS 1024
#define NF 512
#define NH 8
#define NDK 64
#define NHDK 512
#define NROWS (NB*NS)   // 16384

// Scratch (allocation-free rule: __device__ globals)
__device__ float g_q[NB*NH*NS*NDK];   // [B,H,S,DK]
__device__ float g_k[NB*NH*NS*NDK];
__device__ float g_v[NB*NH*NS*NDK];
__device__ float g_z[NROWS*NHDK];     // [B,S,H*DK]

// ---------------------------------------------------------------------------
// Tiled SGEMM: C[m,n] = sum_k A[m,k]*W[n,k]  (A row-major [M,512], W row-major [N,512])
// 128x128 tile, BK=16, 256 threads, 8x8 per thread (split 4+4 rows/cols).
// ---------------------------------------------------------------------------

__global__ __launch_bounds__(256, 2)
void qkv_gemm_kernel(const float* __restrict__ x,
                     const float* __restrict__ Wq, const float* __restrict__ bq,
                     const float* __restrict__ Wk, const float* __restrict__ bk,
                     const float* __restrict__ Wv, const float* __restrict__ bv)
{
    __shared__ float As[16][132];
    __shared__ float Bs[16][132];

    const float* W; const float* bias; float* out;
    if (blockIdx.z == 0)      { W = Wq; bias = bq; out = g_q; }
    else if (blockIdx.z == 1) { W = Wk; bias = bk; out = g_k; }
    else                      { W = Wv; bias = bv; out = g_v; }

    const int tid = threadIdx.x;
    const int tx = tid & 15;
    const int ty = tid >> 4;
    const int mBase = blockIdx.x * 128;
    const int nBase = blockIdx.y * 128;

    float acc[8][8];
    #pragma unroll
    for (int i = 0; i < 8; ++i)
        #pragma unroll
        for (int j = 0; j < 8; ++j) acc[i][j] = 0.f;

    for (int k0 = 0; k0 < NF; k0 += 16) {
        float4 av[2], bw[2];
        #pragma unroll
        for (int i = 0; i < 2; ++i) {
            int idx = tid + i * 256;           // 0..511 float4 slots
            int r = idx >> 2, c4 = (idx & 3) << 2;
            av[i] = *(const float4*)(x + (mBase + r) * NF + k0 + c4);
            bw[i] = *(const float4*)(W + (nBase + r) * NF + k0 + c4);
        }
        __syncthreads();
        #pragma unroll
        for (int i = 0; i < 2; ++i) {
            int idx = tid + i * 256;
            int r = idx >> 2, c4 = (idx & 3) << 2;
            As[c4+0][r] = av[i].x; As[c4+1][r] = av[i].y;
            As[c4+2][r] = av[i].z; As[c4+3][r] = av[i].w;
            Bs[c4+0][r] = bw[i].x; Bs[c4+1][r] = bw[i].y;
            Bs[c4+2][r] = bw[i].z; Bs[c4+3][r] = bw[i].w;
        }
        __syncthreads();
        #pragma unroll
        for (int kk = 0; kk < 16; ++kk) {
            float a[8], b[8];
            *(float4*)&a[0] = *(const float4*)&As[kk][ty*4];
            *(float4*)&a[4] = *(const float4*)&As[kk][64 + ty*4];
            *(float4*)&b[0] = *(const float4*)&Bs[kk][tx*4];
            *(float4*)&b[4] = *(const float4*)&Bs[kk][64 + tx*4];
            #pragma unroll
            for (int i = 0; i < 8; ++i)
                #pragma unroll
                for (int j = 0; j < 8; ++j)
                    acc[i][j] += a[i] * b[j];
        }
    }

    // Epilogue: write to [B,H,S,DK], add bias[h*64+d]
    #pragma unroll
    for (int i = 0; i < 8; ++i) {
        int m = mBase + ty*4 + (i & 3) + ((i >> 2) << 6);
        int b = m >> 10, s = m & 1023;
        #pragma unroll
        for (int jc = 0; jc < 2; ++jc) {
            int n = nBase + tx*4 + jc*64;
            int h = n >> 6, d = n & 63;
            float4 r;
            r.x = acc[i][jc*4+0] + bias[n+0];
            r.y = acc[i][jc*4+1] + bias[n+1];
            r.z = acc[i][jc*4+2] + bias[n+2];
            r.w = acc[i][jc*4+3] + bias[n+3];
            *(float4*)(out + ((b*NH + h)*NS + s) * NDK + d) = r;
        }
    }
}

__global__ __launch_bounds__(256, 2)
void out_gemm_kernel(const float* __restrict__ WOw, const float* __restrict__ WOb,
                     float* __restrict__ outp)
{
    __shared__ float As[16][132];
    __shared__ float Bs[16][132];

    const int tid = threadIdx.x;
    const int tx = tid & 15;
    const int ty = tid >> 4;
    const int mBase = blockIdx.x * 128;
    const int nBase = blockIdx.y * 128;

    float acc[8][8];
    #pragma unroll
    for (int i = 0; i < 8; ++i)
        #pragma unroll
        for (int j = 0; j < 8; ++j) acc[i][j] = 0.f;

    for (int k0 = 0; k0 < NHDK; k0 += 16) {
        float4 av[2], bw[2];
        #pragma unroll
        for (int i = 0; i < 2; ++i) {
            int idx = tid + i * 256;
            int r = idx >> 2, c4 = (idx & 3) << 2;
            av[i] = *(const float4*)(g_z + (mBase + r) * NHDK + k0 + c4);
            bw[i] = *(const float4*)(WOw + (nBase + r) * NHDK + k0 + c4);
        }
        __syncthreads();
        #pragma unroll
        for (int i = 0; i < 2; ++i) {
            int idx = tid + i * 256;
            int r = idx >> 2, c4 = (idx & 3) << 2;
            As[c4+0][r] = av[i].x; As[c4+1][r] = av[i].y;
            As[c4+2][r] = av[i].z; As[c4+3][r] = av[i].w;
            Bs[c4+0][r] = bw[i].x; Bs[c4+1][r] = bw[i].y;
            Bs[c4+2][r] = bw[i].z; Bs[c4+3][r] = bw[i].w;
        }
        __syncthreads();
        #pragma unroll
        for (int kk = 0; kk < 16; ++kk) {
            float a[8], b[8];
            *(float4*)&a[0] = *(const float4*)&As[kk][ty*4];
            *(float4*)&a[4] = *(const float4*)&As[kk][64 + ty*4];
            *(float4*)&b[0] = *(const float4*)&Bs[kk][tx*4];
            *(float4*)&b[4] = *(const float4*)&Bs[kk][64 + tx*4];
            #pragma unroll
            for (int i = 0; i < 8; ++i)
                #pragma unroll
                for (int j = 0; j < 8; ++j)
                    acc[i][j] += a[i] * b[j];
        }
    }

    #pragma unroll
    for (int i = 0; i < 8; ++i) {
        int m = mBase + ty*4 + (i & 3) + ((i >> 2) << 6);
        #pragma unroll
        for (int jc = 0; jc < 2; ++jc) {
            int n = nBase + tx*4 + jc*64;
            float4 r;
            r.x = acc[i][jc*4+0] + WOb[n+0];
            r.y = acc[i][jc*4+1] + WOb[n+1];
            r.z = acc[i][jc*4+2] + WOb[n+2];
            r.w = acc[i][jc*4+3] + WOb[n+3];
            *(float4*)(outp + m * NF + n) = r;
        }
    }
}

// ---------------------------------------------------------------------------
// Flash attention (fp32, online softmax). One block = 64 query rows of one (b,h).
// 128 threads: 16 row-groups x 8 col-groups; each thread owns 4 rows x (4+4) cols.
// ---------------------------------------------------------------------------

__global__ __launch_bounds__(128)
void attn_kernel(const int* __restrict__ xlen)
{
    extern __shared__ float sm[];
    float* Qts = sm;               // [64 d][68]  (Q transposed: d-major)
    float* Kts = sm + 64*68;       // [64 d][68]  (K transposed: d-major)
    float* Vs  = sm + 2*64*68;     // [64 k][68]
    float* Ss  = sm + 3*64*68;     // [64 q][68]  scores / probs
    __shared__ float m_s[64], l_s[64], corr_s[64];

    const int tid = threadIdx.x;
    const int rg = tid >> 3;            // 0..15
    const int cg = tid & 7;             // 0..7
    const int r0 = rg << 2;             // 4 consecutive rows
    const int c0a = cg << 2;            // col chunk A
    const int c0b = 32 + (cg << 2);     // col chunk B

    const int bh = blockIdx.y;
    const int b = bh >> 3;
    const int h = bh & 7;
    const float* Q = g_q + bh * NS * NDK + blockIdx.x * 64 * NDK;
    const float* K = g_k + bh * NS * NDK;
    const float* V = g_v + bh * NS * NDK;
    const int lim = xlen[b] - 1;        // key positions >= lim are masked

    // Load 64x64 Q tile transposed into smem
    #pragma unroll
    for (int it = 0; it < 8; ++it) {
        int i = tid + it * 128;          // float4 slot 0..1023
        int q = i >> 4;
        int d0 = (i & 15) << 2;
        float4 t = *(const float4*)(Q + q * NDK + d0);
        Qts[(d0+0)*68 + q] = t.x;
        Qts[(d0+1)*68 + q] = t.y;
        Qts[(d0+2)*68 + q] = t.z;
        Qts[(d0+3)*68 + q] = t.w;
    }
    if (tid < 64) { m_s[tid] = -1e30f; l_s[tid] = 0.f; }

    float o[4][8];
    #pragma unroll
    for (int i = 0; i < 4; ++i)
        #pragma unroll
        for (int j = 0; j < 8; ++j) o[i][j] = 0.f;

    for (int kt = 0; kt < NS/64; ++kt) {
        __syncthreads();   // protect smem reuse from previous iteration
        const float* Kp = K + kt * 64 * NDK;
        const float* Vp = V + kt * 64 * NDK;
        #pragma unroll
        for (int it = 0; it < 8; ++it) {
            int i = tid + it * 128;
            int k = i >> 4;
            int d0 = (i & 15) << 2;
            float4 t = *(const float4*)(Kp + k * NDK + d0);
            Kts[(d0+0)*68 + k] = t.x;
            Kts[(d0+1)*68 + k] = t.y;
            Kts[(d0+2)*68 + k] = t.z;
            Kts[(d0+3)*68 + k] = t.w;
            float4 u = *(const float4*)(Vp + k * NDK + d0);
            *(float4*)&Vs[k*68 + d0] = u;
        }
        __syncthreads();

        // Scores: S = Q K^T  (64x64x64)
        float sf[4][8];
        #pragma unroll
        for (int i = 0; i < 4; ++i)
            #pragma unroll
            for (int j = 0; j < 8; ++j) sf[i][j] = 0.f;

        #pragma unroll 8
        for (int d = 0; d < 64; ++d) {
            float a[4], kb[8];
            *(float4*)&a[0]  = *(const float4*)&Qts[d*68 + r0];
            *(float4*)&kb[0] = *(const float4*)&Kts[d*68 + c0a];
            *(float4*)&kb[4] = *(const float4*)&Kts[d*68 + c0b];
            #pragma unroll
            for (int i = 0; i < 4; ++i)
                #pragma unroll
                for (int j = 0; j < 8; ++j)
                    sf[i][j] += a[i] * kb[j];
        }

        // Scale + additive mask (matches reference: score/sqrt(DK) + (-999999))
        const int kbase = kt * 64;
        #pragma unroll
        for (int i = 0; i < 4; ++i) {
            float4 w0, w1;
            w0.x = sf[i][0]*0.125f + ((kbase + c0a + 0) >= lim ? -999999.0f : 0.0f);
            w0.y = sf[i][1]*0.125f + ((kbase + c0a + 1) >= lim ? -999999.0f : 0.0f);
            w0.z = sf[i][2]*0.125f + ((kbase + c0a + 2) >= lim ? -999999.0f : 0.0f);
            w0.w = sf[i][3]*0.125f + ((kbase + c0a + 3) >= lim ? -999999.0f : 0.0f);
            w1.x = sf[i][4]*0.125f + ((kbase + c0b + 0) >= lim ? -999999.0f : 0.0f);
            w1.y = sf[i][5]*0.125f + ((kbase + c0b + 1) >= lim ? -999999.0f : 0.0f);
            w1.z = sf[i][6]*0.125f + ((kbase + c0b + 2) >= lim ? -999999.0f : 0.0f);
            w1.w = sf[i][7]*0.125f + ((kbase + c0b + 3) >= lim ? -999999.0f : 0.0f);
            *(float4*)&Ss[(r0+i)*68 + c0a] = w0;
            *(float4*)&Ss[(r0+i)*68 + c0b] = w1;
        }
        __syncthreads();

        // Online softmax, one thread per row; lane*5 stagger -> conflict-free banks
        if (tid < 64) {
            const int row = tid;
            const int off = (tid * 5) & 63;
            float mold = m_s[row];
            float mx = mold;
            #pragma unroll
            for (int c = 0; c < 64; ++c) {
                int cc = (c + off) & 63;
                mx = fmaxf(mx, Ss[row*68 + cc]);
            }
            float corr = __expf(mold - mx);
            float sum = 0.f;
            #pragma unroll
            for (int c = 0; c < 64; ++c) {
                int cc = (c + off) & 63;
                float p = __expf(Ss[row*68 + cc] - mx);
                Ss[row*68 + cc] = p;
                sum += p;
            }
            m_s[row] = mx;
            corr_s[row] = corr;
            l_s[row] = l_s[row] * corr + sum;
        }
        __syncthreads();

        // Rescale running O, then O += P * V  (64x64x64)
        float cr[4];
        #pragma unroll
        for (int i = 0; i < 4; ++i) cr[i] = corr_s[r0+i];
        #pragma unroll
        for (int i = 0; i < 4; ++i)
            #pragma unroll
            for (int j = 0; j < 8; ++j) o[i][j] *= cr[i];

        #pragma unroll 8
        for (int k = 0; k < 64; ++k) {
            float p[4], vv[8];
            #pragma unroll
            for (int i = 0; i < 4; ++i) p[i] = Ss[(r0+i)*68 + k];
            *(float4*)&vv[0] = *(const float4*)&Vs[k*68 + c0a];
            *(float4*)&vv[4] = *(const float4*)&Vs[k*68 + c0b];
            #pragma unroll
            for (int i = 0; i < 4; ++i)
                #pragma unroll
                for (int j = 0; j < 8; ++j)
                    o[i][j] += p[i] * vv[j];
        }
    }

    // Epilogue: normalize and write to g_z [B,S,H*DK]
    float inv[4];
    #pragma unroll
    for (int i = 0; i < 4; ++i) inv[i] = 1.0f / l_s[r0+i];

    const int s_base = blockIdx.x * 64;
    #pragma unroll
    for (int i = 0; i < 4; ++i) {
        int s = s_base + r0 + i;
        float* zp = g_z + (b*NS + s) * NHDK + h * NDK;
        float4 w0, w1;
        w0.x = o[i][0]*inv[i]; w0.y = o[i][1]*inv[i];
        w0.z = o[i][2]*inv[i]; w0.w = o[i][3]*inv[i];
        w1.x = o[i][4]*inv[i]; w1.y = o[i][5]*inv[i];
        w1.z = o[i][6]*inv[i]; w1.w = o[i][7]*inv[i];
        *(float4*)(zp + c0a) = w0;
        *(float4*)(zp + c0b) = w1;
    }
}

// ---------------------------------------------------------------------------

extern "C" void kernel_launch(void* const* d_in, const int* in_sizes, int n_in,
                              void* d_out, int out_size)
{
    (void)in_sizes; (void)n_in; (void)out_size;
    const float* x    = (const float*)d_in[0];
    const int*   xlen = (const int*)  d_in[1];
    const float* WQw  = (const float*)d_in[2];
    const float* WQb  = (const float*)d_in[3];
    const float* WKw  = (const float*)d_in[4];
    const float* WKb  = (const float*)d_in[5];
    const float* WVw  = (const float*)d_in[6];
    const float* WVb  = (const float*)d_in[7];
    const float* WOw  = (const float*)d_in[8];
    const float* WOb  = (const float*)d_in[9];
    float* outp = (float*)d_out;

    const int attn_smem = 4 * 64 * 68 * (int)sizeof(float);   // 69632 B
    cudaFuncSetAttribute(attn_kernel, cudaFuncAttributeMaxDynamicSharedMemorySize, attn_smem);

    qkv_gemm_kernel<<<dim3(NROWS/128, NHDK/128, 3), 256>>>(x, WQw, WQb, WKw, WKb, WVw, WVb);
    attn_kernel<<<dim3(NS/64, NB*NH), 128, attn_smem>>>(xlen);
    out_gemm_kernel<<<dim3(NROWS/128, NF/128), 256>>>(WOw, WOb, outp);
}

// round 2
// speedup vs baseline: 1.4697x; 1.4697x over previous
#include <cuda_runtime.h>

#define NB 16
#define NS 1024
#define NF 512
#define NH 8
#define NDK 64
#define NHDK 512
#define NROWS (NB*NS)   // 16384

// Scratch (allocation-free rule: __device__ globals)
__device__ float g_q[NB*NH*NS*NDK];   // [B,H,S,DK]
__device__ float g_k[NB*NH*NS*NDK];
__device__ float g_v[NB*NH*NS*NDK];
__device__ float g_z[NROWS*NHDK];     // [B,S,H*DK]

// ---------------------------------------------------------------------------
// Tiled SGEMM: C[m,n] = sum_k A[m,k]*W[n,k]  (A row-major [M,512], W row-major [N,512])
// 128x128 tile, BK=16, 256 threads, 8x8 per thread (split 4+4 rows/cols).
// K/V blocks whose sequence rows are entirely masked (s >= lim, lim>0) early-out.
// ---------------------------------------------------------------------------

__global__ __launch_bounds__(256, 2)
void qkv_gemm_kernel(const float* __restrict__ x,
                     const float* __restrict__ Wq, const float* __restrict__ bq,
                     const float* __restrict__ Wk, const float* __restrict__ bk,
                     const float* __restrict__ Wv, const float* __restrict__ bv,
                     const int* __restrict__ xlen)
{
    __shared__ float As[16][132];
    __shared__ float Bs[16][132];

    const int mBase = blockIdx.x * 128;
    const int nBase = blockIdx.y * 128;

    const float* W; const float* bias; float* out;
    if (blockIdx.z == 0)      { W = Wq; bias = bq; out = g_q; }
    else if (blockIdx.z == 1) { W = Wk; bias = bk; out = g_k; }
    else                      { W = Wv; bias = bv; out = g_v; }

    // Skip masked K/V rows: rows s >= lim of K/V are never read by attention
    // when lim > 0 (their probabilities are exactly 0 after softmax underflow).
    if (blockIdx.z != 0) {
        const int bb = mBase >> 10;
        const int lim = xlen[bb] - 1;
        if (lim > 0 && (mBase & 1023) >= lim) return;
    }

    const int tid = threadIdx.x;
    const int tx = tid & 15;
    const int ty = tid >> 4;

    float acc[8][8];
    #pragma unroll
    for (int i = 0; i < 8; ++i)
        #pragma unroll
        for (int j = 0; j < 8; ++j) acc[i][j] = 0.f;

    for (int k0 = 0; k0 < NF; k0 += 16) {
        float4 av[2], bw[2];
        #pragma unroll
        for (int i = 0; i < 2; ++i) {
            int idx = tid + i * 256;           // 0..511 float4 slots
            int r = idx >> 2, c4 = (idx & 3) << 2;
            av[i] = *(const float4*)(x + (mBase + r) * NF + k0 + c4);
            bw[i] = *(const float4*)(W + (nBase + r) * NF + k0 + c4);
        }
        __syncthreads();
        #pragma unroll
        for (int i = 0; i < 2; ++i) {
            int idx = tid + i * 256;
            int r = idx >> 2, c4 = (idx & 3) << 2;
            As[c4+0][r] = av[i].x; As[c4+1][r] = av[i].y;
            As[c4+2][r] = av[i].z; As[c4+3][r] = av[i].w;
            Bs[c4+0][r] = bw[i].x; Bs[c4+1][r] = bw[i].y;
            Bs[c4+2][r] = bw[i].z; Bs[c4+3][r] = bw[i].w;
        }
        __syncthreads();
        #pragma unroll
        for (int kk = 0; kk < 16; ++kk) {
            float a[8], b[8];
            *(float4*)&a[0] = *(const float4*)&As[kk][ty*4];
            *(float4*)&a[4] = *(const float4*)&As[kk][64 + ty*4];
            *(float4*)&b[0] = *(const float4*)&Bs[kk][tx*4];
            *(float4*)&b[4] = *(const float4*)&Bs[kk][64 + tx*4];
            #pragma unroll
            for (int i = 0; i < 8; ++i)
                #pragma unroll
                for (int j = 0; j < 8; ++j)
                    acc[i][j] += a[i] * b[j];
        }
    }

    // Epilogue: write to [B,H,S,DK], add bias[h*64+d]
    #pragma unroll
    for (int i = 0; i < 8; ++i) {
        int m = mBase + ty*4 + (i & 3) + ((i >> 2) << 6);
        int b = m >> 10, s = m & 1023;
        #pragma unroll
        for (int jc = 0; jc < 2; ++jc) {
            int n = nBase + tx*4 + jc*64;
            int h = n >> 6, d = n & 63;
            float4 r;
            r.x = acc[i][jc*4+0] + bias[n+0];
            r.y = acc[i][jc*4+1] + bias[n+1];
            r.z = acc[i][jc*4+2] + bias[n+2];
            r.w = acc[i][jc*4+3] + bias[n+3];
            *(float4*)(out + ((b*NH + h)*NS + s) * NDK + d) = r;
        }
    }
}

__global__ __launch_bounds__(256, 2)
void out_gemm_kernel(const float* __restrict__ WOw, const float* __restrict__ WOb,
                     float* __restrict__ outp)
{
    __shared__ float As[16][132];
    __shared__ float Bs[16][132];

    const int tid = threadIdx.x;
    const int tx = tid & 15;
    const int ty = tid >> 4;
    const int mBase = blockIdx.x * 128;
    const int nBase = blockIdx.y * 128;

    float acc[8][8];
    #pragma unroll
    for (int i = 0; i < 8; ++i)
        #pragma unroll
        for (int j = 0; j < 8; ++j) acc[i][j] = 0.f;

    for (int k0 = 0; k0 < NHDK; k0 += 16) {
        float4 av[2], bw[2];
        #pragma unroll
        for (int i = 0; i < 2; ++i) {
            int idx = tid + i * 256;
            int r = idx >> 2, c4 = (idx & 3) << 2;
            av[i] = *(const float4*)(g_z + (mBase + r) * NHDK + k0 + c4);
            bw[i] = *(const float4*)(WOw + (nBase + r) * NHDK + k0 + c4);
        }
        __syncthreads();
        #pragma unroll
        for (int i = 0; i < 2; ++i) {
            int idx = tid + i * 256;
            int r = idx >> 2, c4 = (idx & 3) << 2;
            As[c4+0][r] = av[i].x; As[c4+1][r] = av[i].y;
            As[c4+2][r] = av[i].z; As[c4+3][r] = av[i].w;
            Bs[c4+0][r] = bw[i].x; Bs[c4+1][r] = bw[i].y;
            Bs[c4+2][r] = bw[i].z; Bs[c4+3][r] = bw[i].w;
        }
        __syncthreads();
        #pragma unroll
        for (int kk = 0; kk < 16; ++kk) {
            float a[8], b[8];
            *(float4*)&a[0] = *(const float4*)&As[kk][ty*4];
            *(float4*)&a[4] = *(const float4*)&As[kk][64 + ty*4];
            *(float4*)&b[0] = *(const float4*)&Bs[kk][tx*4];
            *(float4*)&b[4] = *(const float4*)&Bs[kk][64 + tx*4];
            #pragma unroll
            for (int i = 0; i < 8; ++i)
                #pragma unroll
                for (int j = 0; j < 8; ++j)
                    acc[i][j] += a[i] * b[j];
        }
    }

    #pragma unroll
    for (int i = 0; i < 8; ++i) {
        int m = mBase + ty*4 + (i & 3) + ((i >> 2) << 6);
        #pragma unroll
        for (int jc = 0; jc < 2; ++jc) {
            int n = nBase + tx*4 + jc*64;
            float4 r;
            r.x = acc[i][jc*4+0] + WOb[n+0];
            r.y = acc[i][jc*4+1] + WOb[n+1];
            r.z = acc[i][jc*4+2] + WOb[n+2];
            r.w = acc[i][jc*4+3] + WOb[n+3];
            *(float4*)(outp + m * NF + n) = r;
        }
    }
}

// ---------------------------------------------------------------------------
// Flash attention (fp32, online softmax). One block = 64 query rows of one (b,h).
// 128 threads: 16 row-groups x 8 col-groups; each thread owns 4 rows x (4+4) cols.
// Key tiles entirely beyond lim (lim>0) are skipped: their softmax weights are
// exactly 0.0f (exp underflow), so max/sum/PV are bitwise unaffected.
// ---------------------------------------------------------------------------

__global__ __launch_bounds__(128)
void attn_kernel(const int* __restrict__ xlen)
{
    extern __shared__ float sm[];
    float* Qts = sm;               // [64 d][68]  (Q transposed: d-major)
    float* Kts = sm + 64*68;       // [64 d][68]  (K transposed: d-major)
    float* Vs  = sm + 2*64*68;     // [64 k][68]
    float* Ss  = sm + 3*64*68;     // [64 q][68]  scores / probs
    __shared__ float m_s[64], l_s[64], corr_s[64];

    const int tid = threadIdx.x;
    const int rg = tid >> 3;            // 0..15
    const int cg = tid & 7;             // 0..7
    const int r0 = rg << 2;             // 4 consecutive rows
    const int c0a = cg << 2;            // col chunk A
    const int c0b = 32 + (cg << 2);     // col chunk B

    const int bh = blockIdx.y;
    const int b = bh >> 3;
    const int h = bh & 7;
    const float* Q = g_q + bh * NS * NDK + blockIdx.x * 64 * NDK;
    const float* K = g_k + bh * NS * NDK;
    const float* V = g_v + bh * NS * NDK;
    const int lim = xlen[b] - 1;        // key positions >= lim are masked

    // Number of 64-key tiles that actually contribute:
    //  - lim > 0: tiles past lim have weight exp(-~1e6) == 0.0f exactly -> skip.
    //  - lim <= 0: all keys masked identically; constant shift cancels in
    //    softmax -> must process all tiles.
    const int nkt = (lim > 0) ? min(NS/64, (lim + 63) >> 6) : (NS/64);

    // Load 64x64 Q tile transposed into smem
    #pragma unroll
    for (int it = 0; it < 8; ++it) {
        int i = tid + it * 128;          // float4 slot 0..1023
        int q = i >> 4;
        int d0 = (i & 15) << 2;
        float4 t = *(const float4*)(Q + q * NDK + d0);
        Qts[(d0+0)*68 + q] = t.x;
        Qts[(d0+1)*68 + q] = t.y;
        Qts[(d0+2)*68 + q] = t.z;
        Qts[(d0+3)*68 + q] = t.w;
    }
    if (tid < 64) { m_s[tid] = -1e30f; l_s[tid] = 0.f; }

    float o[4][8];
    #pragma unroll
    for (int i = 0; i < 4; ++i)
        #pragma unroll
        for (int j = 0; j < 8; ++j) o[i][j] = 0.f;

    for (int kt = 0; kt < nkt; ++kt) {
        __syncthreads();   // protect smem reuse from previous iteration
        const float* Kp = K + kt * 64 * NDK;
        const float* Vp = V + kt * 64 * NDK;
        #pragma unroll
        for (int it = 0; it < 8; ++it) {
            int i = tid + it * 128;
            int k = i >> 4;
            int d0 = (i & 15) << 2;
            float4 t = *(const float4*)(Kp + k * NDK + d0);
            Kts[(d0+0)*68 + k] = t.x;
            Kts[(d0+1)*68 + k] = t.y;
            Kts[(d0+2)*68 + k] = t.z;
            Kts[(d0+3)*68 + k] = t.w;
            float4 u = *(const float4*)(Vp + k * NDK + d0);
            *(float4*)&Vs[k*68 + d0] = u;
        }
        __syncthreads();

        // Scores: S = Q K^T  (64x64x64)
        float sf[4][8];
        #pragma unroll
        for (int i = 0; i < 4; ++i)
            #pragma unroll
            for (int j = 0; j < 8; ++j) sf[i][j] = 0.f;

        #pragma unroll 8
        for (int d = 0; d < 64; ++d) {
            float a[4], kb[8];
            *(float4*)&a[0]  = *(const float4*)&Qts[d*68 + r0];
            *(float4*)&kb[0] = *(const float4*)&Kts[d*68 + c0a];
            *(float4*)&kb[4] = *(const float4*)&Kts[d*68 + c0b];
            #pragma unroll
            for (int i = 0; i < 4; ++i)
                #pragma unroll
                for (int j = 0; j < 8; ++j)
                    sf[i][j] += a[i] * kb[j];
        }

        // Scale + additive mask (matches reference: score/sqrt(DK) + (-999999))
        const int kbase = kt * 64;
        #pragma unroll
        for (int i = 0; i < 4; ++i) {
            float4 w0, w1;
            w0.x = sf[i][0]*0.125f + ((kbase + c0a + 0) >= lim ? -999999.0f : 0.0f);
            w0.y = sf[i][1]*0.125f + ((kbase + c0a + 1) >= lim ? -999999.0f : 0.0f);
            w0.z = sf[i][2]*0.125f + ((kbase + c0a + 2) >= lim ? -999999.0f : 0.0f);
            w0.w = sf[i][3]*0.125f + ((kbase + c0a + 3) >= lim ? -999999.0f : 0.0f);
            w1.x = sf[i][4]*0.125f + ((kbase + c0b + 0) >= lim ? -999999.0f : 0.0f);
            w1.y = sf[i][5]*0.125f + ((kbase + c0b + 1) >= lim ? -999999.0f : 0.0f);
            w1.z = sf[i][6]*0.125f + ((kbase + c0b + 2) >= lim ? -999999.0f : 0.0f);
            w1.w = sf[i][7]*0.125f + ((kbase + c0b + 3) >= lim ? -999999.0f : 0.0f);
            *(float4*)&Ss[(r0+i)*68 + c0a] = w0;
            *(float4*)&Ss[(r0+i)*68 + c0b] = w1;
        }
        __syncthreads();

        // Online softmax, one thread per row; lane*5 stagger -> conflict-free banks
        if (tid < 64) {
            const int row = tid;
            const int off = (tid * 5) & 63;
            float mold = m_s[row];
            float mx = mold;
            #pragma unroll
            for (int c = 0; c < 64; ++c) {
                int cc = (c + off) & 63;
                mx = fmaxf(mx, Ss[row*68 + cc]);
            }
            float corr = __expf(mold - mx);
            float sum = 0.f;
            #pragma unroll
            for (int c = 0; c < 64; ++c) {
                int cc = (c + off) & 63;
                float p = __expf(Ss[row*68 + cc] - mx);
                Ss[row*68 + cc] = p;
                sum += p;
            }
            m_s[row] = mx;
            corr_s[row] = corr;
            l_s[row] = l_s[row] * corr + sum;
        }
        __syncthreads();

        // Rescale running O, then O += P * V  (64x64x64)
        float cr[4];
        #pragma unroll
        for (int i = 0; i < 4; ++i) cr[i] = corr_s[r0+i];
        #pragma unroll
        for (int i = 0; i < 4; ++i)
            #pragma unroll
            for (int j = 0; j < 8; ++j) o[i][j] *= cr[i];

        #pragma unroll 8
        for (int k = 0; k < 64; ++k) {
            float p[4], vv[8];
            #pragma unroll
            for (int i = 0; i < 4; ++i) p[i] = Ss[(r0+i)*68 + k];
            *(float4*)&vv[0] = *(const float4*)&Vs[k*68 + c0a];
            *(float4*)&vv[4] = *(const float4*)&Vs[k*68 + c0b];
            #pragma unroll
            for (int i = 0; i < 4; ++i)
                #pragma unroll
                for (int j = 0; j < 8; ++j)
                    o[i][j] += p[i] * vv[j];
        }
    }

    // Epilogue: normalize and write to g_z [B,S,H*DK]
    float inv[4];
    #pragma unroll
    for (int i = 0; i < 4; ++i) inv[i] = 1.0f / l_s[r0+i];

    const int s_base = blockIdx.x * 64;
    #pragma unroll
    for (int i = 0; i < 4; ++i) {
        int s = s_base + r0 + i;
        float* zp = g_z + (b*NS + s) * NHDK + h * NDK;
        float4 w0, w1;
        w0.x = o[i][0]*inv[i]; w0.y = o[i][1]*inv[i];
        w0.z = o[i][2]*inv[i]; w0.w = o[i][3]*inv[i];
        w1.x = o[i][4]*inv[i]; w1.y = o[i][5]*inv[i];
        w1.z = o[i][6]*inv[i]; w1.w = o[i][7]*inv[i];
        *(float4*)(zp + c0a) = w0;
        *(float4*)(zp + c0b) = w1;
    }
}

// ---------------------------------------------------------------------------

extern "C" void kernel_launch(void* const* d_in, const int* in_sizes, int n_in,
                              void* d_out, int out_size)
{
    (void)in_sizes; (void)n_in; (void)out_size;
    const float* x    = (const float*)d_in[0];
    const int*   xlen = (const int*)  d_in[1];
    const float* WQw  = (const float*)d_in[2];
    const float* WQb  = (const float*)d_in[3];
    const float* WKw  = (const float*)d_in[4];
    const float* WKb  = (const float*)d_in[5];
    const float* WVw  = (const float*)d_in[6];
    const float* WVb  = (const float*)d_in[7];
    const float* WOw  = (const float*)d_in[8];
    const float* WOb  = (const float*)d_in[9];
    float* outp = (float*)d_out;

    const int attn_smem = 4 * 64 * 68 * (int)sizeof(float);   // 69632 B
    cudaFuncSetAttribute(attn_kernel, cudaFuncAttributeMaxDynamicSharedMemorySize, attn_smem);

    qkv_gemm_kernel<<<dim3(NROWS/128, NHDK/128, 3), 256>>>(x, WQw, WQb, WKw, WKb, WVw, WVb, xlen);
    attn_kernel<<<dim3(NS/64, NB*NH), 128, attn_smem>>>(xlen);
    out_gemm_kernel<<<dim3(NROWS/128, NF/128), 256>>>(WOw, WOb, outp);
}

// round 3
// speedup vs baseline: 4.8536x; 3.3025x over previous
#include <cuda_runtime.h>
#include <cstdint>

#define NB 16
#define NS 1024
#define NF 512
#define NH 8
#define NDK 64
#define NHDK 512
#define NROWS (NB*NS)   // 16384

// Scratch (allocation-free rule: __device__ globals)
__device__ float g_q[NB*NH*NS*NDK];   // [B,H,S,DK]
__device__ float g_k[NB*NH*NS*NDK];
__device__ float g_v[NB*NH*NS*NDK];
__device__ float g_z[NROWS*NHDK];     // [B,S,H*DK]

// ---------------------------------------------------------------------------
// tf32 helpers
// ---------------------------------------------------------------------------
__device__ __forceinline__ uint32_t f2tf32(float f) {
    uint32_t u;
    asm("cvt.rna.tf32.f32 %0, %1;" : "=r"(u) : "f"(f));
    return u;
}

__device__ __forceinline__ void mma_tf32(float c[4], const uint32_t a[4], const uint32_t b[2]) {
    asm volatile("mma.sync.aligned.m16n8k8.row.col.f32.tf32.tf32.f32 "
        "{%0,%1,%2,%3}, {%4,%5,%6,%7}, {%8,%9}, {%0,%1,%2,%3};"
        : "+f"(c[0]), "+f"(c[1]), "+f"(c[2]), "+f"(c[3])
        : "r"(a[0]), "r"(a[1]), "r"(a[2]), "r"(a[3]), "r"(b[0]), "r"(b[1]));
}

// ---------------------------------------------------------------------------
// tf32 tensor-core GEMM: C[m,n] = sum_k A[m,k]*W[n,k]  (A [M,512], W [N,512], row-major)
// Block tile 128x128, BK=32, 256 threads = 8 warps (2m x 4n), warp tile 64x32.
// ---------------------------------------------------------------------------

#define GSTRIDE 36   // smem row stride (floats): bank = (4g+t) distinct -> conflict-free

__global__ __launch_bounds__(256, 2)
void qkv_gemm_tc(const float* __restrict__ x,
                 const float* __restrict__ Wq, const float* __restrict__ bq,
                 const float* __restrict__ Wk, const float* __restrict__ bk,
                 const float* __restrict__ Wv, const float* __restrict__ bv,
                 const int* __restrict__ xlen)
{
    __shared__ uint32_t As[128 * GSTRIDE];
    __shared__ uint32_t Bs[128 * GSTRIDE];

    const int mBase = blockIdx.x * 128;
    const int nBase = blockIdx.y * 128;

    const float* W; const float* bias; float* out;
    if (blockIdx.z == 0)      { W = Wq; bias = bq; out = g_q; }
    else if (blockIdx.z == 1) { W = Wk; bias = bk; out = g_v; }
    else                      { W = Wv; bias = bv; out = g_v; }
    if (blockIdx.z == 1) out = g_k;  // (kept explicit below)
    if (blockIdx.z == 0) out = g_q; else if (blockIdx.z == 1) out = g_k; else out = g_v;

    // Skip masked K/V rows (their softmax weights are exactly 0 downstream).
    if (blockIdx.z != 0) {
        const int bb = mBase >> 10;
        const int lim = xlen[bb] - 1;
        if (lim > 0 && (mBase & 1023) >= lim) return;
    }

    const int tid = threadIdx.x;
    const int lane = tid & 31;
    const int wid = tid >> 5;
    const int wm = wid >> 2;          // 0..1
    const int wn = wid & 3;           // 0..3
    const int g = lane >> 2, t = lane & 3;

    const int lr = tid >> 3;          // 0..31
    const int lc = (tid & 7) << 2;    // 0,4,...,28

    float acc[4][4][4];
    #pragma unroll
    for (int i = 0; i < 4; ++i)
        #pragma unroll
        for (int j = 0; j < 4; ++j)
            #pragma unroll
            for (int e = 0; e < 4; ++e) acc[i][j][e] = 0.f;

    for (int k0 = 0; k0 < NF; k0 += 32) {
        float4 av[4], bw[4];
        #pragma unroll
        for (int it = 0; it < 4; ++it) {
            av[it] = *(const float4*)(x + (mBase + it*32 + lr) * NF + k0 + lc);
            bw[it] = *(const float4*)(W + (nBase + it*32 + lr) * NF + k0 + lc);
        }
        __syncthreads();
        #pragma unroll
        for (int it = 0; it < 4; ++it) {
            uint32_t* da = &As[(it*32 + lr) * GSTRIDE + lc];
            da[0] = f2tf32(av[it].x); da[1] = f2tf32(av[it].y);
            da[2] = f2tf32(av[it].z); da[3] = f2tf32(av[it].w);
            uint32_t* db = &Bs[(it*32 + lr) * GSTRIDE + lc];
            db[0] = f2tf32(bw[it].x); db[1] = f2tf32(bw[it].y);
            db[2] = f2tf32(bw[it].z); db[3] = f2tf32(bw[it].w);
        }
        __syncthreads();

        #pragma unroll
        for (int ks = 0; ks < 4; ++ks) {
            uint32_t af[4][4];
            #pragma unroll
            for (int im = 0; im < 4; ++im) {
                int m = 64*wm + 16*im;
                af[im][0] = As[(m + g    ) * GSTRIDE + 8*ks + t];
                af[im][1] = As[(m + g + 8) * GSTRIDE + 8*ks + t];
                af[im][2] = As[(m + g    ) * GSTRIDE + 8*ks + t + 4];
                af[im][3] = As[(m + g + 8) * GSTRIDE + 8*ks + t + 4];
            }
            #pragma unroll
            for (int jn = 0; jn < 4; ++jn) {
                int n = 32*wn + 8*jn;
                uint32_t bf[2];
                bf[0] = Bs[(n + g) * GSTRIDE + 8*ks + t];
                bf[1] = Bs[(n + g) * GSTRIDE + 8*ks + t + 4];
                #pragma unroll
                for (int im = 0; im < 4; ++im)
                    mma_tf32(acc[im][jn], af[im], bf);
            }
        }
    }

    // Epilogue: write [B,H,S,DK] with bias
    #pragma unroll
    for (int im = 0; im < 4; ++im) {
        int mlo = mBase + 64*wm + 16*im + g;
        int mhi = mlo + 8;
        int blo = mlo >> 10, slo = mlo & 1023;
        int bhi = mhi >> 10, shi = mhi & 1023;
        #pragma unroll
        for (int jn = 0; jn < 4; ++jn) {
            int n = nBase + 32*wn + 8*jn + 2*t;
            int h = n >> 6, d = n & 63;
            float bx = bias[n], by = bias[n+1];
            float2 v0 = make_float2(acc[im][jn][0] + bx, acc[im][jn][1] + by);
            float2 v1 = make_float2(acc[im][jn][2] + bx, acc[im][jn][3] + by);
            *(float2*)(out + ((blo*NH + h)*NS + slo) * NDK + d) = v0;
            *(float2*)(out + ((bhi*NH + h)*NS + shi) * NDK + d) = v1;
        }
    }
}

__global__ __launch_bounds__(256, 2)
void out_gemm_tc(const float* __restrict__ WOw, const float* __restrict__ WOb,
                 float* __restrict__ outp)
{
    __shared__ uint32_t As[128 * GSTRIDE];
    __shared__ uint32_t Bs[128 * GSTRIDE];

    const int mBase = blockIdx.x * 128;
    const int nBase = blockIdx.y * 128;

    const int tid = threadIdx.x;
    const int lane = tid & 31;
    const int wid = tid >> 5;
    const int wm = wid >> 2;
    const int wn = wid & 3;
    const int g = lane >> 2, t = lane & 3;

    const int lr = tid >> 3;
    const int lc = (tid & 7) << 2;

    float acc[4][4][4];
    #pragma unroll
    for (int i = 0; i < 4; ++i)
        #pragma unroll
        for (int j = 0; j < 4; ++j)
            #pragma unroll
            for (int e = 0; e < 4; ++e) acc[i][j][e] = 0.f;

    for (int k0 = 0; k0 < NHDK; k0 += 32) {
        float4 av[4], bw[4];
        #pragma unroll
        for (int it = 0; it < 4; ++it) {
            av[it] = *(const float4*)(g_z + (mBase + it*32 + lr) * NHDK + k0 + lc);
            bw[it] = *(const float4*)(WOw + (nBase + it*32 + lr) * NHDK + k0 + lc);
        }
        __syncthreads();
        #pragma unroll
        for (int it = 0; it < 4; ++it) {
            uint32_t* da = &As[(it*32 + lr) * GSTRIDE + lc];
            da[0] = f2tf32(av[it].x); da[1] = f2tf32(av[it].y);
            da[2] = f2tf32(av[it].z); da[3] = f2tf32(av[it].w);
            uint32_t* db = &Bs[(it*32 + lr) * GSTRIDE + lc];
            db[0] = f2tf32(bw[it].x); db[1] = f2tf32(bw[it].y);
            db[2] = f2tf32(bw[it].z); db[3] = f2tf32(bw[it].w);
        }
        __syncthreads();

        #pragma unroll
        for (int ks = 0; ks < 4; ++ks) {
            uint32_t af[4][4];
            #pragma unroll
            for (int im = 0; im < 4; ++im) {
                int m = 64*wm + 16*im;
                af[im][0] = As[(m + g    ) * GSTRIDE + 8*ks + t];
                af[im][1] = As[(m + g + 8) * GSTRIDE + 8*ks + t];
                af[im][2] = As[(m + g    ) * GSTRIDE + 8*ks + t + 4];
                af[im][3] = As[(m + g + 8) * GSTRIDE + 8*ks + t + 4];
            }
            #pragma unroll
            for (int jn = 0; jn < 4; ++jn) {
                int n = 32*wn + 8*jn;
                uint32_t bf[2];
                bf[0] = Bs[(n + g) * GSTRIDE + 8*ks + t];
                bf[1] = Bs[(n + g) * GSTRIDE + 8*ks + t + 4];
                #pragma unroll
                for (int im = 0; im < 4; ++im)
                    mma_tf32(acc[im][jn], af[im], bf);
            }
        }
    }

    #pragma unroll
    for (int im = 0; im < 4; ++im) {
        int mlo = mBase + 64*wm + 16*im + g;
        int mhi = mlo + 8;
        #pragma unroll
        for (int jn = 0; jn < 4; ++jn) {
            int n = nBase + 32*wn + 8*jn + 2*t;
            float bx = WOb[n], by = WOb[n+1];
            float2 v0 = make_float2(acc[im][jn][0] + bx, acc[im][jn][1] + by);
            float2 v1 = make_float2(acc[im][jn][2] + bx, acc[im][jn][3] + by);
            *(float2*)(outp + mlo * NF + n) = v0;
            *(float2*)(outp + mhi * NF + n) = v1;
        }
    }
}

// ---------------------------------------------------------------------------
// Flash attention with tf32 tensor cores. Block = 64 queries of one (b,h),
// 4 warps x 16 query rows. Online softmax fully in registers (quad shfl).
// P re-fragmented via per-warp-private smem (syncwarp only).
// ---------------------------------------------------------------------------

#define KSTRIDE 68
#define VSTRIDE 72   // 72 % 32 == 8 -> conflict-free V B-frag loads
#define PSTRIDE 68

__global__ __launch_bounds__(128)
void attn_tc_kernel(const int* __restrict__ xlen)
{
    extern __shared__ float sm[];
    float* Ks = sm;                           // [64][68]   (also Q staging)
    float* Vs = sm + 64*KSTRIDE;              // [64][72]
    float* Ps = sm + 64*KSTRIDE + 64*VSTRIDE; // [4][16][68]

    const int tid = threadIdx.x;
    const int w = tid >> 5;
    const int lane = tid & 31;
    const int g = lane >> 2, t = lane & 3;

    const int bh = blockIdx.y;
    const int b = bh >> 3;
    const int h = bh & 7;
    const float* Q = g_q + bh * NS * NDK + blockIdx.x * 64 * NDK;
    const float* K = g_k + bh * NS * NDK;
    const float* V = g_v + bh * NS * NDK;
    const int lim = xlen[b] - 1;
    const int nkt = (lim > 0) ? min(NS/64, (lim + 63) >> 6) : (NS/64);

    // Stage Q into Ks, then pull fragments into registers (tf32-rounded)
    #pragma unroll
    for (int it = 0; it < 8; ++it) {
        int i = tid + it * 128;
        int r = i >> 4, c4 = (i & 15) << 2;
        float4 tq = *(const float4*)(Q + r * NDK + c4);
        float* dst = &Ks[r * KSTRIDE + c4];
        dst[0] = tq.x; dst[1] = tq.y; dst[2] = tq.z; dst[3] = tq.w;
    }
    __syncthreads();

    uint32_t qa[8][4];
    {
        const int r = 16*w + g;
        #pragma unroll
        for (int j = 0; j < 8; ++j) {
            qa[j][0] = f2tf32(Ks[ r      * KSTRIDE + 8*j + t    ]);
            qa[j][1] = f2tf32(Ks[(r + 8) * KSTRIDE + 8*j + t    ]);
            qa[j][2] = f2tf32(Ks[ r      * KSTRIDE + 8*j + t + 4]);
            qa[j][3] = f2tf32(Ks[(r + 8) * KSTRIDE + 8*j + t + 4]);
        }
    }

    float o[8][4];
    #pragma unroll
    for (int nf = 0; nf < 8; ++nf)
        #pragma unroll
        for (int e = 0; e < 4; ++e) o[nf][e] = 0.f;

    float m0 = -1e30f, m1 = -1e30f, l0 = 0.f, l1 = 0.f;
    float* Pw = Ps + w * 16 * PSTRIDE;

    for (int kt = 0; kt < nkt; ++kt) {
        __syncthreads();   // previous tile's consumers done (also covers Q staging)
        const float* Kp = K + kt * 64 * NDK;
        const float* Vp = V + kt * 64 * NDK;
        #pragma unroll
        for (int it = 0; it < 8; ++it) {
            int i = tid + it * 128;
            int r = i >> 4, c4 = (i & 15) << 2;
            float4 tk = *(const float4*)(Kp + r * NDK + c4);
            float* kd = &Ks[r * KSTRIDE + c4];
            kd[0] = __uint_as_float(f2tf32(tk.x));
            kd[1] = __uint_as_float(f2tf32(tk.y));
            kd[2] = __uint_as_float(f2tf32(tk.z));
            kd[3] = __uint_as_float(f2tf32(tk.w));
            float4 tv = *(const float4*)(Vp + r * NDK + c4);
            float* vd = &Vs[r * VSTRIDE + c4];
            vd[0] = __uint_as_float(f2tf32(tv.x));
            vd[1] = __uint_as_float(f2tf32(tv.y));
            vd[2] = __uint_as_float(f2tf32(tv.z));
            vd[3] = __uint_as_float(f2tf32(tv.w));
        }
        __syncthreads();

        // S = Q K^T : 16x64 per warp
        float sc[8][4];
        #pragma unroll
        for (int nf = 0; nf < 8; ++nf)
            #pragma unroll
            for (int e = 0; e < 4; ++e) sc[nf][e] = 0.f;

        #pragma unroll
        for (int j = 0; j < 8; ++j) {
            #pragma unroll
            for (int nf = 0; nf < 8; ++nf) {
                uint32_t kb[2];
                kb[0] = __float_as_uint(Ks[(8*nf + g) * KSTRIDE + 8*j + t    ]);
                kb[1] = __float_as_uint(Ks[(8*nf + g) * KSTRIDE + 8*j + t + 4]);
                mma_tf32(sc[nf], qa[j], kb);
            }
        }

        // Scale + mask, row max (registers + quad shfl)
        const int kb0 = kt * 64;
        float mxA = -1e30f, mxB = -1e30f;
        #pragma unroll
        for (int nf = 0; nf < 8; ++nf) {
            int key = kb0 + 8*nf + 2*t;
            float msk0 = (key     >= lim) ? -999999.0f : 0.0f;
            float msk1 = (key + 1 >= lim) ? -999999.0f : 0.0f;
            sc[nf][0] = sc[nf][0] * 0.125f + msk0;
            sc[nf][1] = sc[nf][1] * 0.125f + msk1;
            sc[nf][2] = sc[nf][2] * 0.125f + msk0;
            sc[nf][3] = sc[nf][3] * 0.125f + msk1;
            mxA = fmaxf(mxA, fmaxf(sc[nf][0], sc[nf][1]));
            mxB = fmaxf(mxB, fmaxf(sc[nf][2], sc[nf][3]));
        }
        mxA = fmaxf(mxA, __shfl_xor_sync(0xffffffffu, mxA, 1));
        mxA = fmaxf(mxA, __shfl_xor_sync(0xffffffffu, mxA, 2));
        mxB = fmaxf(mxB, __shfl_xor_sync(0xffffffffu, mxB, 1));
        mxB = fmaxf(mxB, __shfl_xor_sync(0xffffffffu, mxB, 2));

        float mn0 = fmaxf(m0, mxA), mn1 = fmaxf(m1, mxB);
        float corr0 = __expf(m0 - mn0), corr1 = __expf(m1 - mn1);
        m0 = mn0; m1 = mn1;

        float sumA = 0.f, sumB = 0.f;
        #pragma unroll
        for (int nf = 0; nf < 8; ++nf) {
            float p0 = __expf(sc[nf][0] - m0);
            float p1 = __expf(sc[nf][1] - m0);
            float p2 = __expf(sc[nf][2] - m1);
            float p3 = __expf(sc[nf][3] - m1);
            sumA += p0 + p1;
            sumB += p2 + p3;
            int c = 8*nf + 2*t;
            *(float2*)&Pw[ g      * PSTRIDE + c] =
                make_float2(__uint_as_float(f2tf32(p0)), __uint_as_float(f2tf32(p1)));
            *(float2*)&Pw[(g + 8) * PSTRIDE + c] =
                make_float2(__uint_as_float(f2tf32(p2)), __uint_as_float(f2tf32(p3)));
        }
        sumA += __shfl_xor_sync(0xffffffffu, sumA, 1);
        sumA += __shfl_xor_sync(0xffffffffu, sumA, 2);
        sumB += __shfl_xor_sync(0xffffffffu, sumB, 1);
        sumB += __shfl_xor_sync(0xffffffffu, sumB, 2);
        l0 = l0 * corr0 + sumA;
        l1 = l1 * corr1 + sumB;

        #pragma unroll
        for (int nf = 0; nf < 8; ++nf) {
            o[nf][0] *= corr0; o[nf][1] *= corr0;
            o[nf][2] *= corr1; o[nf][3] *= corr1;
        }
        __syncwarp();

        // O += P V : P per-warp-private (16x64), V shared
        #pragma unroll
        for (int j = 0; j < 8; ++j) {
            uint32_t pa[4];
            pa[0] = __float_as_uint(Pw[ g      * PSTRIDE + 8*j + t    ]);
            pa[1] = __float_as_uint(Pw[(g + 8) * PSTRIDE + 8*j + t    ]);
            pa[2] = __float_as_uint(Pw[ g      * PSTRIDE + 8*j + t + 4]);
            pa[3] = __float_as_uint(Pw[(g + 8) * PSTRIDE + 8*j + t + 4]);
            #pragma unroll
            for (int nf = 0; nf < 8; ++nf) {
                uint32_t vb[2];
                vb[0] = __float_as_uint(Vs[(8*j + t    ) * VSTRIDE + 8*nf + g]);
                vb[1] = __float_as_uint(Vs[(8*j + t + 4) * VSTRIDE + 8*nf + g]);
                mma_tf32(o[nf], pa, vb);
            }
        }
    }

    // Epilogue: normalize, write g_z [B,S,H*DK]
    const float inv0 = 1.0f / l0, inv1 = 1.0f / l1;
    const int slo = blockIdx.x * 64 + 16*w + g;
    const int shi = slo + 8;
    float* zlo = g_z + (b*NS + slo) * NHDK + h * NDK;
    float* zhi = g_z + (b*NS + shi) * NHDK + h * NDK;
    #pragma unroll
    for (int nf = 0; nf < 8; ++nf) {
        int d = 8*nf + 2*t;
        *(float2*)(zlo + d) = make_float2(o[nf][0] * inv0, o[nf][1] * inv0);
        *(float2*)(zhi + d) = make_float2(o[nf][2] * inv1, o[nf][3] * inv1);
    }
}

// ---------------------------------------------------------------------------

extern "C" void kernel_launch(void* const* d_in, const int* in_sizes, int n_in,
                              void* d_out, int out_size)
{
    (void)in_sizes; (void)n_in; (void)out_size;
    const float* x    = (const float*)d_in[0];
    const int*   xlen = (const int*)  d_in[1];
    const float* WQw  = (const float*)d_in[2];
    const float* WQb  = (const float*)d_in[3];
    const float* WKw  = (const float*)d_in[4];
    const float* WKb  = (const float*)d_in[5];
    const float* WVw  = (const float*)d_in[6];
    const float* WVb  = (const float*)d_in[7];
    const float* WOw  = (const float*)d_in[8];
    const float* WOb  = (const float*)d_in[9];
    float* outp = (float*)d_out;

    const int attn_smem = (64*KSTRIDE + 64*VSTRIDE + 4*16*PSTRIDE) * (int)sizeof(float); // 53248
    cudaFuncSetAttribute(attn_tc_kernel, cudaFuncAttributeMaxDynamicSharedMemorySize, attn_smem);

    qkv_gemm_tc<<<dim3(NROWS/128, NHDK/128, 3), 256>>>(x, WQw, WQb, WKw, WKb, WVw, WVb, xlen);
    attn_tc_kernel<<<dim3(NS/64, NB*NH), 128, attn_smem>>>(xlen);
    out_gemm_tc<<<dim3(NROWS/128, NF/128), 256>>>(WOw, WOb, outp);
}